// round 17
// baseline (speedup 1.0000x reference)
#include <cuda_runtime.h>
#include <cuda_bf16.h>
#include <cstdint>

// ---------------- problem constants ----------------
#define Wd   384
#define Hd   384
#define Cd   256
#define HWd  (Wd * Hd)          // 147456
#define NOBJ 16
#define NP   128
#define NN   2048
#define NKP  2048               // N_OBJ * N_P key points
#define NPTS (NKP + NOBJ * NN)  // 34816 total sampled points
#define NTILES 16               // 2048 / 128 n-tiles per object

// ---------------- device scratch (static: no allocations allowed) ----------------
__device__ __nv_bfloat16 g_imgTh[(size_t)HWd * Cd]; // [s][c] transposed image, bf16 (75 MB)
__device__ __nv_bfloat16 g_Fh[(size_t)NPTS * Cd];   // [pt][c] sampled features bf16 (17.8 MB)
__device__ int   g_cnt [NOBJ * NP * NTILES];
__device__ float g_dsum[NOBJ * NP * NTILES];
__device__ float g_dmin[NOBJ * NP * NTILES];
__device__ float g_m[NOBJ];

// =================================================================
// Kernel 0: m[o] = (sum(point_set_2[o]) >= 0). 16 blocks, float4.
// =================================================================
__global__ __launch_bounds__(256)
void m_kernel(const float* __restrict__ ps2) {
    __shared__ float red[8];
    const int o   = blockIdx.x;
    const int tid = threadIdx.x;
    const float4* p = (const float4*)(ps2 + (size_t)o * (NN * 2));
    float s = 0.0f;
    #pragma unroll
    for (int i = 0; i < 16; i++) {
        const float4 v = p[tid + i * 256];
        s += v.x + v.y + v.z + v.w;
    }
    #pragma unroll
    for (int off = 16; off; off >>= 1) s += __shfl_xor_sync(0xffffffffu, s, off);
    if ((tid & 31) == 0) red[tid >> 5] = s;
    __syncthreads();
    if (tid == 0) {
        float t = 0.0f;
        #pragma unroll
        for (int w = 0; w < 8; w++) t += red[w];
        g_m[o] = (t >= 0.0f) ? 1.0f : 0.0f;
    }
}

// =================================================================
// Kernel 1: transpose feats [C,H,W] -> g_imgTh [H*W, C] in bf16.
// =================================================================
__global__ void transpose_kernel(const float* __restrict__ in) {
    __shared__ float tile[32][33];
    const int bs = blockIdx.x * 32;     // s base (pixel index)
    const int bc = blockIdx.y * 32;     // c base
    const int tx = threadIdx.x;         // 0..7
    const int ty = threadIdx.y;         // 0..31

    const float4 v = *(const float4*)(in + (size_t)(bc + ty) * HWd + bs + tx * 4);
    tile[ty][tx * 4 + 0] = v.x;
    tile[ty][tx * 4 + 1] = v.y;
    tile[ty][tx * 4 + 2] = v.z;
    tile[ty][tx * 4 + 3] = v.w;
    __syncthreads();

    const float w0 = tile[tx * 4 + 0][ty];
    const float w1 = tile[tx * 4 + 1][ty];
    const float w2 = tile[tx * 4 + 2][ty];
    const float w3 = tile[tx * 4 + 3][ty];
    uint2 o;
    {
        const __nv_bfloat162 lo = __floats2bfloat162_rn(w0, w1);
        const __nv_bfloat162 hi = __floats2bfloat162_rn(w2, w3);
        o.x = *(const unsigned*)&lo;
        o.y = *(const unsigned*)&hi;
    }
    *(uint2*)(g_imgTh + (size_t)(bs + ty) * Cd + bc + tx * 4) = o;
}

// =================================================================
// Kernel 2: bilinear grid-sample from bf16 image -> bf16 features.
// Block = 8 points x 32 lanes (8 channels each).
// =================================================================
__global__ __launch_bounds__(256)
void sample_kernel(const float* __restrict__ kp,
                   const float* __restrict__ ps2) {
    const int lane = threadIdx.x;                     // 0..31, 8 channels each
    const int pt   = blockIdx.x * 8 + threadIdx.y;    // 0..34815

    const float* src = (pt < NKP) ? (kp + (size_t)pt * 2)
                                  : (ps2 + (size_t)(pt - NKP) * 2);
    const float px = src[0];
    const float py = src[1];

    // exact reference math (grid_sample, align_corners=False)
    const float gx = 2.0f * (px * (1.0f / 384.0f)) - 1.0f;
    const float gy = 2.0f * (py * (1.0f / 384.0f)) - 1.0f;
    const float x  = ((gx + 1.0f) * 384.0f - 1.0f) * 0.5f;
    const float y  = ((gy + 1.0f) * 384.0f - 1.0f) * 0.5f;

    const float x0f = floorf(x), y0f = floorf(y);
    const float wx1 = x - x0f,   wy1 = y - y0f;
    const float wx0 = 1.0f - wx1, wy0 = 1.0f - wy1;
    const int x0 = (int)x0f, y0 = (int)y0f;
    const int x1 = x0 + 1,   y1 = y0 + 1;

    const float vx0 = (x0 >= 0 && x0 < Wd) ? 1.0f : 0.0f;
    const float vx1 = (x1 >= 0 && x1 < Wd) ? 1.0f : 0.0f;
    const float vy0 = (y0 >= 0 && y0 < Hd) ? 1.0f : 0.0f;
    const float vy1 = (y1 >= 0 && y1 < Hd) ? 1.0f : 0.0f;

    const float w00 = wx0 * wy0 * vx0 * vy0;
    const float w10 = wx1 * wy0 * vx1 * vy0;
    const float w01 = wx0 * wy1 * vx0 * vy1;
    const float w11 = wx1 * wy1 * vx1 * vy1;

    const int xc0 = min(max(x0, 0), Wd - 1);
    const int xc1 = min(max(x1, 0), Wd - 1);
    const int yc0 = min(max(y0, 0), Hd - 1);
    const int yc1 = min(max(y1, 0), Hd - 1);

    const size_t coff = (size_t)lane * 8;
    const uint4 r00 = *(const uint4*)(g_imgTh + ((size_t)(yc0 * Wd + xc0)) * Cd + coff);
    const uint4 r10 = *(const uint4*)(g_imgTh + ((size_t)(yc0 * Wd + xc1)) * Cd + coff);
    const uint4 r01 = *(const uint4*)(g_imgTh + ((size_t)(yc1 * Wd + xc0)) * Cd + coff);
    const uint4 r11 = *(const uint4*)(g_imgTh + ((size_t)(yc1 * Wd + xc1)) * Cd + coff);

    uint4 o4;
    #pragma unroll
    for (int q = 0; q < 4; q++) {
        const unsigned u00 = (&r00.x)[q];
        const unsigned u10 = (&r10.x)[q];
        const unsigned u01 = (&r01.x)[q];
        const unsigned u11 = (&r11.x)[q];
        const float2 f00 = __bfloat1622float2(*(const __nv_bfloat162*)&u00);
        const float2 f10 = __bfloat1622float2(*(const __nv_bfloat162*)&u10);
        const float2 f01 = __bfloat1622float2(*(const __nv_bfloat162*)&u01);
        const float2 f11 = __bfloat1622float2(*(const __nv_bfloat162*)&u11);
        const float oa = w00 * f00.x + w10 * f10.x + w01 * f01.x + w11 * f11.x;
        const float ob = w00 * f00.y + w10 * f10.y + w01 * f01.y + w11 * f11.y;
        const __nv_bfloat162 pk = __floats2bfloat162_rn(oa, ob);
        (&o4.x)[q] = *(const unsigned*)&pk;
    }

    *(uint4*)(g_Fh + (size_t)pt * Cd + coff) = o4;
}

// =================================================================
// Kernel 3: HMMA GEMM sign + distance + masked reduction.
// OCCUPANCY VERSION: 512 threads/CTA, 16 warps as 4(m) x 4(n),
// warp tile 32x32 (2 mtiles x 4 ntiles). Accumulators 32 regs ->
// __launch_bounds__(512,2) -> 2 CTAs/SM -> 32 warps (50% occ),
// double the latency-hiding of the R14 version. Same CTA tile
// (128p x 128n, K=256 in 4 cp.async double-buffered chunks), same
// fragment mapping, same epilogue math.
// =================================================================
__device__ __forceinline__ uint32_t smem_u32(const void* p) {
    uint32_t a;
    asm("{ .reg .u64 t; cvta.to.shared.u64 t, %1; cvt.u32.u64 %0, t; }" : "=r"(a) : "l"(p));
    return a;
}
#define LDSM_X4(r0, r1, r2, r3, addr) \
    asm volatile("ldmatrix.sync.aligned.m8n8.x4.shared.b16 {%0,%1,%2,%3}, [%4];" \
                 : "=r"(r0), "=r"(r1), "=r"(r2), "=r"(r3) : "r"(addr))
#define MMA16816(d, a, b) \
    asm volatile("mma.sync.aligned.m16n8k16.row.col.f32.bf16.bf16.f32 " \
                 "{%0,%1,%2,%3}, {%4,%5,%6,%7}, {%8,%9}, {%0,%1,%2,%3};" \
                 : "+f"((d)[0]), "+f"((d)[1]), "+f"((d)[2]), "+f"((d)[3]) \
                 : "r"((a)[0]), "r"((a)[1]), "r"((a)[2]), "r"((a)[3]), \
                   "r"((b)[0]), "r"((b)[1]))
#define CP_ASYNC16(dst, src) \
    asm volatile("cp.async.cg.shared.global [%0], [%1], 16;" :: "r"(dst), "l"(src))
#define CP_COMMIT() asm volatile("cp.async.commit_group;" ::: "memory")
#define CP_WAIT(n)  asm volatile("cp.async.wait_group %0;" :: "n"(n) : "memory")

// dynamic smem layout (bytes)
#define GSM_A0   0
#define GSM_A1   16384
#define GSM_B0   32768
#define GSM_B1   49152
#define GSM_PTS  65536                       // s1x,s1y,s2x,s2y: 4*512
#define GSM_RED  (GSM_PTS + 2048)            // r_cnt/r_sum/r_min: 3*4*128*4
#define GSM_TOTAL (GSM_RED + 6144)           // 73728 B

__global__ __launch_bounds__(512, 2)
void gemm_mma_kernel(const float* __restrict__ ps1,
                     const float* __restrict__ ps2) {
    extern __shared__ __align__(16) char sm[];
    const uint32_t smb = smem_u32(sm);

    const int o    = blockIdx.y;
    const int nt   = blockIdx.x;
    const int tid  = threadIdx.x;
    const int wid  = tid >> 5;            // 0..15
    const int lane = tid & 31;
    const int warp_m = wid & 3;           // 0..3 (m groups of 32)
    const int warp_n = wid >> 2;          // 0..3 (n groups of 32)
    const int m_base = warp_m * 32;
    const int n_base = warp_n * 32;

    float* s1x = (float*)(sm + GSM_PTS);
    float* s1y = s1x + 128;
    float* s2x = s1y + 128;
    float* s2y = s2x + 128;
    float* r_cnt = (float*)(sm + GSM_RED);          // [4][128]
    float* r_sum = r_cnt + 4 * 128;
    float* r_min = r_sum + 4 * 128;

    if (tid < 128) {
        const size_t i1 = ((size_t)o * NP + tid) * 2;
        s1x[tid] = ps1[i1];
        s1y[tid] = ps1[i1 + 1];
        const size_t i2 = ((size_t)o * NN + nt * 128 + tid) * 2;
        s2x[tid] = ps2[i2];
        s2y[tid] = ps2[i2 + 1];
    }

    const char* gA = (const char*)(g_Fh + (size_t)(o * 128) * Cd);            // [128][512B]
    const char* gB = (const char*)(g_Fh + (size_t)(NKP + o * NN + nt * 128) * Cd);

    float acc[2][4][4];
    #pragma unroll
    for (int mt = 0; mt < 2; mt++)
        #pragma unroll
        for (int nn = 0; nn < 4; nn++)
            #pragma unroll
            for (int q = 0; q < 4; q++) acc[mt][nn][q] = 0.0f;

    // per-lane ldmatrix row/granule bases
    const int rowA = m_base + (lane & 7) + (((lane >> 3) & 1) << 3);  // + mt*16
    const int gA_l = (lane >> 4);                                     // + ks*2
    const int rowB = n_base + (lane & 7) + ((lane >> 4) << 3);        // + half*16
    const int gB_l = ((lane >> 3) & 1);                               // + ks*2

    // precomputed per-thread staging slots (2 granules each per tile)
    uint32_t st_sw[2];
    uint32_t st_go[2];
    #pragma unroll
    for (int j = 0; j < 2; j++) {
        const int idx = j * 512 + tid;        // 0..1023 granules
        const int row = idx >> 3;
        const int g   = idx & 7;
        const uint32_t off = (row << 7) + (g << 4);
        st_sw[j] = off ^ ((off >> 3) & 0x70);
        st_go[j] = row * 512 + g * 16;        // + chunk*128
    }

    // ---- prologue: stage chunk 0 into buffer 0 ----
    #pragma unroll
    for (int j = 0; j < 2; j++) {
        CP_ASYNC16(smb + GSM_A0 + st_sw[j], gA + st_go[j]);
        CP_ASYNC16(smb + GSM_B0 + st_sw[j], gB + st_go[j]);
    }
    CP_COMMIT();

    #pragma unroll
    for (int chunk = 0; chunk < 4; chunk++) {
        const uint32_t bA = smb + ((chunk & 1) ? GSM_A1 : GSM_A0);
        const uint32_t bB = smb + ((chunk & 1) ? GSM_B1 : GSM_B0);

        // issue next chunk into the other buffer (overlaps with compute)
        if (chunk < 3) {
            const uint32_t nA = smb + ((chunk & 1) ? GSM_A0 : GSM_A1);
            const uint32_t nB = smb + ((chunk & 1) ? GSM_B0 : GSM_B1);
            const uint32_t co = (chunk + 1) * 128;
            #pragma unroll
            for (int j = 0; j < 2; j++) {
                CP_ASYNC16(nA + st_sw[j], gA + st_go[j] + co);
                CP_ASYNC16(nB + st_sw[j], gB + st_go[j] + co);
            }
            CP_COMMIT();
            CP_WAIT(1);            // current chunk's group complete
        } else {
            CP_WAIT(0);
        }
        __syncthreads();

        #pragma unroll
        for (int ks = 0; ks < 4; ks++) {          // k16 steps within chunk
            uint32_t afr[2][4], bfr[4][2];
            #pragma unroll
            for (int mt = 0; mt < 2; mt++) {
                const int row = rowA + mt * 16;
                const int g   = ks * 2 + gA_l;
                const uint32_t off = (row << 7) + (g << 4);
                const uint32_t sw  = off ^ ((off >> 3) & 0x70);
                LDSM_X4(afr[mt][0], afr[mt][1], afr[mt][2], afr[mt][3], bA + sw);
            }
            #pragma unroll
            for (int h = 0; h < 2; h++) {
                const int row = rowB + h * 16;
                const int g   = ks * 2 + gB_l;
                const uint32_t off = (row << 7) + (g << 4);
                const uint32_t sw  = off ^ ((off >> 3) & 0x70);
                LDSM_X4(bfr[h * 2][0], bfr[h * 2][1],
                        bfr[h * 2 + 1][0], bfr[h * 2 + 1][1], bB + sw);
            }
            #pragma unroll
            for (int mt = 0; mt < 2; mt++)
                #pragma unroll
                for (int nn = 0; nn < 4; nn++)
                    MMA16816(acc[mt][nn], afr[mt], bfr[nn]);
        }
        __syncthreads();   // buffer reused by the chunk+2 issue
    }

    // ---- epilogue: mask + distance on fragments, quad-shfl n-reduce ----
    #pragma unroll
    for (int mt = 0; mt < 2; mt++) {
        #pragma unroll
        for (int r01 = 0; r01 < 2; r01++) {
            const int p = m_base + mt * 16 + (lane >> 2) + r01 * 8;
            const float px = s1x[p], py = s1y[p];
            float cnt = 0.0f, ds = 0.0f, dm = 3.402823466e38f;
            #pragma unroll
            for (int nn = 0; nn < 4; nn++) {
                const int n = n_base + nn * 8 + 2 * (lane & 3);
                const float c0 = acc[mt][nn][r01 * 2 + 0];
                const float c1 = acc[mt][nn][r01 * 2 + 1];
                if (c0 >= 0.0f) {
                    const float dx = px - s2x[n], dy = py - s2y[n];
                    const float d = sqrtf(dx * dx + dy * dy);
                    cnt += 1.0f; ds += d; dm = fminf(dm, d);
                }
                if (c1 >= 0.0f) {
                    const float dx = px - s2x[n + 1], dy = py - s2y[n + 1];
                    const float d = sqrtf(dx * dx + dy * dy);
                    cnt += 1.0f; ds += d; dm = fminf(dm, d);
                }
            }
            #pragma unroll
            for (int off = 1; off < 4; off <<= 1) {
                cnt += __shfl_xor_sync(0xffffffffu, cnt, off);
                ds  += __shfl_xor_sync(0xffffffffu, ds,  off);
                dm   = fminf(dm, __shfl_xor_sync(0xffffffffu, dm, off));
            }
            if ((lane & 3) == 0) {
                r_cnt[warp_n * 128 + p] = cnt;
                r_sum[warp_n * 128 + p] = ds;
                r_min[warp_n * 128 + p] = dm;
            }
        }
    }
    __syncthreads();

    if (tid < 128) {
        const int p = tid;
        float cnt = 0.0f, ds = 0.0f, dm = 3.402823466e38f;
        #pragma unroll
        for (int w = 0; w < 4; w++) {
            cnt += r_cnt[w * 128 + p];
            ds  += r_sum[w * 128 + p];
            dm   = fminf(dm, r_min[w * 128 + p]);
        }
        const int idx = (o * NP + p) * NTILES + nt;
        g_cnt[idx]  = (int)cnt;
        g_dsum[idx] = ds;
        g_dmin[idx] = dm;
    }
}

// =================================================================
// Kernel 4: combine tile partials -> chamfer costs -> scalar loss.
// =================================================================
__global__ __launch_bounds__(512)
void final_kernel(float* __restrict__ out) {
    __shared__ float red[512];
    const int tid = threadIdx.x;

    float local = 0.0f;
    #pragma unroll
    for (int it = 0; it < (NOBJ * NP) / 512; it++) {
        const int cell = it * 512 + tid;
        const int idx0 = cell * NTILES;
        int   cnt  = 0;
        float dsum = 0.0f;
        float dmin = 3.402823466e38f;
        #pragma unroll
        for (int t = 0; t < NTILES; t += 4) {
            const int4   c4 = *(const int4*)  (g_cnt  + idx0 + t);
            const float4 s4 = *(const float4*)(g_dsum + idx0 + t);
            const float4 m4 = *(const float4*)(g_dmin + idx0 + t);
            cnt  += c4.x + c4.y + c4.z + c4.w;
            dsum += s4.x + s4.y + s4.z + s4.w;
            dmin  = fminf(dmin, fminf(fminf(m4.x, m4.y), fminf(m4.z, m4.w)));
        }
        if (cnt > 0)
            local += 0.5f * (dmin + dsum / (float)cnt) * g_m[cell >> 7];
    }
    red[tid] = local;
    __syncthreads();
    for (int s = 256; s > 0; s >>= 1) {
        if (tid < s) red[tid] += red[tid + s];
        __syncthreads();
    }
    if (tid == 0) out[0] = red[0] * (1.0f / (float)(NOBJ * NP));
}

// =================================================================
// kernel_launch: 5 launches, graph-capturable, no allocations,
// no static state.
// =================================================================
extern "C" void kernel_launch(void* const* d_in, const int* in_sizes, int n_in,
                              void* d_out, int out_size) {
    const float* ps1   = nullptr;
    const float* ps2   = nullptr;
    const float* feats = nullptr;
    const float* kp    = nullptr;
    for (int i = 0; i < n_in; i++) {
        if (in_sizes[i] == 37748736)      feats = (const float*)d_in[i];
        else if (in_sizes[i] == 65536)    ps2   = (const float*)d_in[i];
        else if (in_sizes[i] == 4096) {
            if (!ps1) ps1 = (const float*)d_in[i];
            else      kp  = (const float*)d_in[i];
        }
    }
    float* out = (float*)d_out;

    // Non-stream, idempotent; safe during graph capture.
    cudaFuncSetAttribute(gemm_mma_kernel,
                         cudaFuncAttributeMaxDynamicSharedMemorySize, GSM_TOTAL);

    m_kernel<<<NOBJ, 256>>>(ps2);
    transpose_kernel<<<dim3(HWd / 32, Cd / 32), dim3(8, 32)>>>(feats);
    sample_kernel<<<NPTS / 8, dim3(32, 8)>>>(kp, ps2);
    gemm_mma_kernel<<<dim3(NTILES, NOBJ), 512, GSM_TOTAL>>>(ps1, ps2);
    final_kernel<<<1, 512>>>(out);
}